// round 7
// baseline (speedup 1.0000x reference)
#include <cuda_runtime.h>
#include <cuda_bf16.h>
#include <cstdint>
#include <math.h>

#define B_  512
#define Z_  64
#define H_  256
#define T_  64
#define P_  10000
#define G3_ 768
#define BT_ (B_*T_)
#define PPAD 10112   // 79*128
#define KS_ 768      // split-K: [Ah, Ah, Al] x [Wh, Wl, Wh]

// ---------------- scratch (no allocations allowed) ----------------
__device__ float g_h0[B_*H_];
__device__ float g_gx0[G3_];
__device__ float g_y0[BT_*H_];
__device__ float g_gx1[(size_t)BT_*G3_];
__device__ __align__(256) __nv_bfloat16 g_A2y0[(size_t)BT_*KS_];
__device__ __align__(256) __nv_bfloat16 g_A2out[(size_t)BT_*KS_];
__device__ __align__(256) __nv_bfloat16 g_Wb2[(size_t)PPAD*KS_];
__device__ __align__(256) __nv_bfloat16 g_Wih1b2[(size_t)G3_*KS_];
__device__ __align__(256) __nv_bfloat16 g_Wpk0[393216];   // packed scan weights layer 0
__device__ __align__(256) __nv_bfloat16 g_Wpk1[393216];   // packed scan weights layer 1

__device__ __forceinline__ float elu1(float x) {
    return x > 0.f ? x : (__expf(x) - 1.f);
}

__device__ __forceinline__ uint32_t smem_u32(const void* p) {
    uint32_t a;
    asm("{ .reg .u64 t; cvta.to.shared.u64 t, %1; cvt.u32.u64 %0, t; }" : "=r"(a) : "l"(p));
    return a;
}
__device__ __forceinline__ void cp16(uint32_t s, const void* g) {
    asm volatile("cp.async.cg.shared.global [%0], [%1], 16;" :: "r"(s), "l"(g));
}
__device__ __forceinline__ void ldsm4(uint32_t& a0, uint32_t& a1, uint32_t& a2, uint32_t& a3,
                                      uint32_t addr) {
    asm volatile("ldmatrix.sync.aligned.m8n8.x4.shared.b16 {%0,%1,%2,%3}, [%4];"
        : "=r"(a0), "=r"(a1), "=r"(a2), "=r"(a3) : "r"(addr));
}
__device__ __forceinline__ void mma16816(float* d, uint32_t a0, uint32_t a1, uint32_t a2,
                                         uint32_t a3, uint32_t b0, uint32_t b1) {
    asm volatile("mma.sync.aligned.m16n8k16.row.col.f32.bf16.bf16.f32 "
        "{%0,%1,%2,%3}, {%4,%5,%6,%7}, {%8,%9}, {%0,%1,%2,%3};"
        : "+f"(d[0]), "+f"(d[1]), "+f"(d[2]), "+f"(d[3])
        : "r"(a0), "r"(a1), "r"(a2), "r"(a3), "r"(b0), "r"(b1));
}

// ================= bf16 split-K tensor GEMM (unchanged, passing) =================
#define ST_B 49152
#define GSM  (3 * ST_B)
__global__ __launch_bounds__(256, 1) void gemm_mma(
        const __nv_bfloat16* __restrict__ A2, const __nv_bfloat16* __restrict__ B2,
        const float* __restrict__ bias, float* __restrict__ C, int N, int ldc) {
    extern __shared__ char sm[];
    const uint32_t sbase = smem_u32(sm);
    const int tid = threadIdx.x, lane = tid & 31, wid = tid >> 5;
    const int m0t = blockIdx.y << 8, n0t = blockIdx.x << 7;

    uint32_t aSoff[8];
#pragma unroll
    for (int j = 0; j < 8; ++j)
        aSoff[j] = (uint32_t)(tid * 128 + ((j << 4) ^ ((tid & 7) << 4)));
    const char* gAr = (const char*)A2 + (size_t)(m0t + tid) * (KS_ * 2);
    const int brow = tid >> 1, bj0 = (tid & 1) * 4;
    uint32_t bSoff[4];
#pragma unroll
    for (int j = 0; j < 4; ++j)
        bSoff[j] = (uint32_t)(32768 + brow * 128 + (((bj0 + j) << 4) ^ ((brow & 7) << 4)));
    const char* gBr = (const char*)B2 + (size_t)(n0t + brow) * (KS_ * 2) + bj0 * 16;

    const int g = lane >> 3, r = lane & 7;
    const uint32_t rx = r << 4;
    const uint32_t aKbx = (g >> 1) << 4;
    const uint32_t bKbx = (g & 1) << 4;
    uint32_t aRowOff[4], bRowOff[4];
#pragma unroll
    for (int fm = 0; fm < 4; ++fm)
        aRowOff[fm] = (uint32_t)(((wid & 3) * 64 + ((g & 1) << 3) + r + fm * 16) * 128);
#pragma unroll
    for (int p = 0; p < 4; ++p)
        bRowOff[p] = (uint32_t)(32768 + ((wid >> 2) * 64 + ((g >> 1) << 3) + r + p * 16) * 128);

    float acc[4][8][4];
#pragma unroll
    for (int i = 0; i < 4; ++i)
#pragma unroll
        for (int j = 0; j < 8; ++j)
#pragma unroll
            for (int k = 0; k < 4; ++k) acc[i][j][k] = 0.f;

#pragma unroll
    for (int c = 0; c < 2; ++c) {
        const uint32_t sa = sbase + c * ST_B;
#pragma unroll
        for (int j = 0; j < 8; ++j) cp16(sa + aSoff[j], gAr + c * 128 + j * 16);
#pragma unroll
        for (int j = 0; j < 4; ++j) cp16(sa + bSoff[j], gBr + c * 128 + j * 16);
        asm volatile("cp.async.commit_group;");
    }

    int stage = 0, nstage = 2;
    for (int c = 0; c < 12; ++c) {
        if (c < 11) asm volatile("cp.async.wait_group 1;");
        else        asm volatile("cp.async.wait_group 0;");
        __syncthreads();

        if (c + 2 < 12) {
            const uint32_t sa = sbase + nstage * ST_B;
#pragma unroll
            for (int j = 0; j < 8; ++j) cp16(sa + aSoff[j], gAr + (c + 2) * 128 + j * 16);
#pragma unroll
            for (int j = 0; j < 4; ++j) cp16(sa + bSoff[j], gBr + (c + 2) * 128 + j * 16);
            asm volatile("cp.async.commit_group;");
        }

        const uint32_t sB = sbase + stage * ST_B;
#pragma unroll
        for (int kk = 0; kk < 4; ++kk) {
            const uint32_t akoff = ((uint32_t)(kk * 32) + aKbx) ^ rx;
            const uint32_t bkoff = ((uint32_t)(kk * 32) + bKbx) ^ rx;
            uint32_t a[4][4], bb[4][4];
#pragma unroll
            for (int fm = 0; fm < 4; ++fm)
                ldsm4(a[fm][0], a[fm][1], a[fm][2], a[fm][3], sB + aRowOff[fm] + akoff);
#pragma unroll
            for (int p = 0; p < 4; ++p)
                ldsm4(bb[p][0], bb[p][1], bb[p][2], bb[p][3], sB + bRowOff[p] + bkoff);
#pragma unroll
            for (int fm = 0; fm < 4; ++fm)
#pragma unroll
                for (int p = 0; p < 4; ++p) {
                    mma16816(acc[fm][2 * p],     a[fm][0], a[fm][1], a[fm][2], a[fm][3],
                             bb[p][0], bb[p][1]);
                    mma16816(acc[fm][2 * p + 1], a[fm][0], a[fm][1], a[fm][2], a[fm][3],
                             bb[p][2], bb[p][3]);
                }
        }
        stage  = (stage  == 2) ? 0 : stage  + 1;
        nstage = (nstage == 2) ? 0 : nstage + 1;
    }

#pragma unroll
    for (int fm = 0; fm < 4; ++fm) {
        const int mrow = m0t + (wid & 3) * 64 + fm * 16 + (lane >> 2);
        float* c0 = C + (size_t)mrow * ldc;
        float* c1 = C + (size_t)(mrow + 8) * ldc;
#pragma unroll
        for (int bn = 0; bn < 8; ++bn) {
            const int n = n0t + (wid >> 2) * 64 + bn * 8 + (lane & 3) * 2;
            if (n < N) {
                const float bv = bias[n];
                c0[n] = acc[fm][bn][0] + bv;
                c1[n] = acc[fm][bn][2] + bv;
            }
            if (n + 1 < N) {
                const float bv = bias[n + 1];
                c0[n + 1] = acc[fm][bn][1] + bv;
                c1[n + 1] = acc[fm][bn][3] + bv;
            }
        }
    }
}

// ================= tensor-core GRU scan =================
// CTA = 16 batch rows, 256 threads (8 warps). Warp w owns units 32w..32w+31
// (gate rows u, 256+u, 512+u). Per step: gh = [hh|hl](16x512) vs B-stream [Wh|Wl],
// Wh chunks consumed by both hh and hl A-tiles (3-term split).
// SMEM map:
#define SW_A2   0          // 32 tiles x 768B (16 rows x 48B): [0..15]=hh, [16..31]=hl
#define SW_B    24576      // 8 warps x 3 bufs x 6 tiles x 768B = 110592
#define SW_GH   135168     // 16 rows x 776 floats (pitch 3104B) = 49664
#define SW_H    184832     // 16 rows x 256 floats (pitch 1024B) = 16384
#define SCAN_SMEM 201216

__global__ __launch_bounds__(256, 1) void gru_scan_t(
        const __nv_bfloat16* __restrict__ Wpak, const float* __restrict__ bhh,
        const float* __restrict__ gx, int per_bt,
        float* __restrict__ y, int outmode) {
    extern __shared__ char sm[];
    const uint32_t sb = smem_u32(sm);
    const int tid = threadIdx.x, lane = tid & 31, w = tid >> 5;
    const int b0 = blockIdx.x * 16;

    const float bh_r = bhh[tid], bh_z = bhh[256 + tid], bh_n = bhh[512 + tid];
    float cgx_r = 0.f, cgx_z = 0.f, cgx_n = 0.f;
    if (!per_bt) { cgx_r = gx[tid]; cgx_z = gx[256 + tid]; cgx_n = gx[512 + tid]; }

    // init h + A2 (hh tiles 0..15, hl tiles 16..31; tile = unit>>4, col = unit&15)
    for (int r = 0; r < 16; ++r) {
        float h = g_h0[(b0 + r) * H_ + tid];
        *(float*)(sm + SW_H + r * 1024 + tid * 4) = h;
        __nv_bfloat16 hi = __float2bfloat16(h);
        float lo = h - __bfloat162float(hi);
        char* ca = sm + SW_A2 + (tid >> 4) * 768 + r * 48 + (tid & 15) * 2;
        *(__nv_bfloat16*)ca = hi;
        *(__nv_bfloat16*)(ca + 12288) = __float2bfloat16(lo);
    }

    const int g2 = lane >> 3, r8 = lane & 7;
    const uint32_t aoff = (uint32_t)((((g2 & 1) << 3) + r8) * 48 + (g2 >> 1) * 16);
    const uint32_t boff = (uint32_t)((((g2 >> 1) << 3) + r8) * 48 + (g2 & 1) * 16);
    const uint32_t myB = sb + SW_B + w * 13824;
    const char* myW = (const char*)Wpak + (size_t)w * 32 * 3072;

    // prologue: B chunks 0,1 into bufs 0,1 (per-warp private)
#pragma unroll
    for (int c = 0; c < 2; ++c) {
        const char* gsrc = myW + c * 3072;
        uint32_t dstb = myB + c * 4608;
#pragma unroll
        for (int j = 0; j < 6; ++j) {
            int u = lane + j * 32;
            cp16(dstb + (u >> 5) * 768 + ((u & 31) >> 1) * 48 + (u & 1) * 16, gsrc + u * 16);
        }
        asm volatile("cp.async.commit_group;");
    }
    __syncthreads();

    int kcg = 0;   // global ring chunk counter
    for (int step = 0; step < T_; ++step) {
        float acc[12][4];
#pragma unroll
        for (int i = 0; i < 12; ++i) { acc[i][0]=0.f; acc[i][1]=0.f; acc[i][2]=0.f; acc[i][3]=0.f; }

#pragma unroll 4
        for (int kc = 0; kc < 32; ++kc) {
            asm volatile("cp.async.wait_group 1;");
            __syncwarp();
            const uint32_t bbb = myB + (uint32_t)(kcg % 3) * 4608;
            {   // prefetch chunk kcg+2 (data (kcg+2)&31) into buf (kcg+2)%3
                const char* gsrc = myW + ((kcg + 2) & 31) * 3072;
                uint32_t dstb = myB + (uint32_t)((kcg + 2) % 3) * 4608;
#pragma unroll
                for (int j = 0; j < 6; ++j) {
                    int u = lane + j * 32;
                    cp16(dstb + (u >> 5) * 768 + ((u & 31) >> 1) * 48 + (u & 1) * 16,
                         gsrc + u * 16);
                }
                asm volatile("cp.async.commit_group;");
            }
            uint32_t a0[4], a1[4];
            const bool dual = kc < 16;          // Wh chunks pair with hh AND hl
            const int at = dual ? kc : kc - 16; // hh tile index
            ldsm4(a0[0], a0[1], a0[2], a0[3], sb + SW_A2 + at * 768 + aoff);
            if (dual)
                ldsm4(a1[0], a1[1], a1[2], a1[3], sb + SW_A2 + 12288 + kc * 768 + aoff);
#pragma unroll
            for (int nt = 0; nt < 6; ++nt) {
                uint32_t b4[4];
                ldsm4(b4[0], b4[1], b4[2], b4[3], bbb + nt * 768 + boff);
                mma16816(acc[nt*2],     a0[0], a0[1], a0[2], a0[3], b4[0], b4[1]);
                mma16816(acc[nt*2 + 1], a0[0], a0[1], a0[2], a0[3], b4[2], b4[3]);
                if (dual) {
                    mma16816(acc[nt*2],     a1[0], a1[1], a1[2], a1[3], b4[0], b4[1]);
                    mma16816(acc[nt*2 + 1], a1[0], a1[1], a1[2], a1[3], b4[2], b4[3]);
                }
            }
            ++kcg;
        }

        // write gh to smem (warp-local gates, global gate numbering)
        {
            const int r0 = lane >> 2;
#pragma unroll
            for (int nb = 0; nb < 12; ++nb) {
                int nt = nb >> 1, sub = nb & 1;
                int gate = (nt >> 1) * 256 + w * 32 + (nt & 1) * 16 + sub * 8 + 2 * (lane & 3);
                *(float2*)(sm + SW_GH + r0 * 3104 + gate * 4) =
                    make_float2(acc[nb][0], acc[nb][1]);
                *(float2*)(sm + SW_GH + (r0 + 8) * 3104 + gate * 4) =
                    make_float2(acc[nb][2], acc[nb][3]);
            }
        }
        __syncthreads();

        // gate math: thread t = unit t, loop 16 rows
        float xr[16], xz[16], xn[16];
        if (per_bt) {
#pragma unroll
            for (int r = 0; r < 16; ++r) {
                const float* gp = gx + ((size_t)(b0 + r) * T_ + step) * G3_;
                xr[r] = gp[tid]; xz[r] = gp[256 + tid]; xn[r] = gp[512 + tid];
            }
        }
#pragma unroll
        for (int r = 0; r < 16; ++r) {
            const char* ghp = sm + SW_GH + r * 3104;
            float hr = *(const float*)(ghp + tid * 4) + bh_r;
            float hz = *(const float*)(ghp + (256 + tid) * 4) + bh_z;
            float hn = *(const float*)(ghp + (512 + tid) * 4) + bh_n;
            float xr_ = per_bt ? xr[r] : cgx_r;
            float xz_ = per_bt ? xz[r] : cgx_z;
            float xn_ = per_bt ? xn[r] : cgx_n;
            float rg = 1.f / (1.f + __expf(-(xr_ + hr)));
            float ug = 1.f / (1.f + __expf(-(xz_ + hz)));
            float ng = tanhf(xn_ + rg * hn);
            float* hp = (float*)(sm + SW_H + r * 1024 + tid * 4);
            float hnew = (1.f - ug) * ng + ug * (*hp);
            *hp = hnew;
            __nv_bfloat16 hi = __float2bfloat16(hnew);
            float lo = hnew - __bfloat162float(hi);
            char* ca = sm + SW_A2 + (tid >> 4) * 768 + r * 48 + (tid & 15) * 2;
            *(__nv_bfloat16*)ca = hi;
            *(__nv_bfloat16*)(ca + 12288) = __float2bfloat16(lo);
            size_t row = (size_t)(b0 + r) * T_ + step;
            if (outmode == 0) {
                g_A2y0[row * KS_ + tid]       = hi;
                g_A2y0[row * KS_ + 256 + tid] = hi;
                g_A2y0[row * KS_ + 512 + tid] = __float2bfloat16(lo);
            } else {
                y[row * H_ + tid] = hnew;
            }
        }
        __syncthreads();
    }
}

// ---------------- prep kernels ----------------
__global__ void k_h0(const float* __restrict__ z, const float* __restrict__ Wi,
                     const float* __restrict__ bi) {
    int idx = blockIdx.x * 256 + threadIdx.x;
    int b = idx >> 8, h = idx & 255;
    float s = bi[h];
    const float* zr = z + b * Z_;
    const float* wr = Wi + h * Z_;
#pragma unroll 16
    for (int i = 0; i < Z_; i++) s += zr[i] * wr[i];
    g_h0[idx] = elu1(s);
}

__global__ void k_gx0(const float* __restrict__ emb, const float* __restrict__ Wih,
                      const float* __restrict__ bih) {
    int gg = blockIdx.x * 256 + threadIdx.x;
    float s = bih[gg];
    const float* wr = Wih + gg * H_;
#pragma unroll 8
    for (int i = 0; i < H_; i++) s += emb[i] * wr[i];
    g_gx0[gg] = s;
}

// pack Whh into per-warp ldsm tile stream: O[((w*32+kc)*6+nt)*256 + row*16 + col]
// kc<16 -> hi(W[gate][kc*16+col]) ; kc>=16 -> lo(W[gate][(kc-16)*16+col])
// gate = (nt>>1)*256 + w*32 + (nt&1)*16 + row
__global__ void k_wpack_scan(const float* __restrict__ W, __nv_bfloat16* __restrict__ O) {
    int idx = blockIdx.x * 256 + threadIdx.x;   // 393216
    int col = idx & 15;
    int row = (idx >> 4) & 15;
    int t3 = idx >> 8;
    int nt = t3 % 6;
    int t2 = t3 / 6;
    int kc = t2 & 31, w = t2 >> 5;
    int gate = (nt >> 1) * 256 + w * 32 + (nt & 1) * 16 + row;
    __nv_bfloat16 v;
    if (kc < 16) {
        v = __float2bfloat16(W[gate * 256 + kc * 16 + col]);
    } else {
        float x = W[gate * 256 + (kc - 16) * 16 + col];
        __nv_bfloat16 hi = __float2bfloat16(x);
        v = __float2bfloat16(x - __bfloat162float(hi));
    }
    O[idx] = v;
}

// weights for GEMMs: [Wh, Wl, Wh]
__global__ void k_wsplit(const float* __restrict__ W, __nv_bfloat16* __restrict__ O, int N) {
    int idx = blockIdx.x * 256 + threadIdx.x;
    int row = idx >> 8, col = idx & 255;
    float x = (row < N) ? W[row * 256 + col] : 0.f;
    __nv_bfloat16 hi = __float2bfloat16(x);
    float lo = x - __bfloat162float(hi);
    size_t base = (size_t)row * KS_;
    O[base + col]       = hi;
    O[base + 256 + col] = __float2bfloat16(lo);
    O[base + 512 + col] = hi;
}

// ---------------- LayerNorm + ELU -> split bf16 ----------------
__global__ void k_ln_elu(const float* __restrict__ y, const float* __restrict__ lng,
                         const float* __restrict__ lnb) {
    int warp = threadIdx.x >> 5, lane = threadIdx.x & 31;
    int row = blockIdx.x * 8 + warp;
    const float* p = y + (size_t)row * H_;
    float v[8], s = 0.f, sq = 0.f;
#pragma unroll
    for (int i = 0; i < 8; i++) { v[i] = p[lane + 32*i]; s += v[i]; sq += v[i]*v[i]; }
#pragma unroll
    for (int o = 16; o; o >>= 1) {
        s  += __shfl_xor_sync(0xffffffffu, s,  o);
        sq += __shfl_xor_sync(0xffffffffu, sq, o);
    }
    float mu  = s  * (1.f / H_);
    float var = sq * (1.f / H_) - mu * mu;
    float inv = rsqrtf(var + 1e-5f);
#pragma unroll
    for (int i = 0; i < 8; i++) {
        int c = lane + 32*i;
        float t = elu1((v[i] - mu) * inv * lng[c] + lnb[c]);
        __nv_bfloat16 hi = __float2bfloat16(t);
        float lo = t - __bfloat162float(hi);
        size_t base = (size_t)row * KS_;
        g_A2out[base + c]       = hi;
        g_A2out[base + 256 + c] = hi;
        g_A2out[base + 512 + c] = __float2bfloat16(lo);
    }
}

// ---------------- launch ----------------
extern "C" void kernel_launch(void* const* d_in, const int* in_sizes, int n_in,
                              void* d_out, int out_size) {
    const float* z      = (const float*)d_in[0];
    const float* W_init = (const float*)d_in[1];
    const float* b_init = (const float*)d_in[2];
    const float* emb    = (const float*)d_in[3];
    const float* W_ih0  = (const float*)d_in[4];
    const float* W_hh0  = (const float*)d_in[5];
    const float* b_ih0  = (const float*)d_in[6];
    const float* b_hh0  = (const float*)d_in[7];
    const float* W_ih1  = (const float*)d_in[8];
    const float* W_hh1  = (const float*)d_in[9];
    const float* b_ih1  = (const float*)d_in[10];
    const float* b_hh1  = (const float*)d_in[11];
    const float* ln_g   = (const float*)d_in[12];
    const float* ln_b   = (const float*)d_in[13];
    const float* W_out  = (const float*)d_in[14];
    const float* b_out  = (const float*)d_in[15];

    float *p_y0, *p_gx0, *p_gx1;
    __nv_bfloat16 *p_A2y0, *p_A2out, *p_Wb2, *p_Wih1b2, *p_Wpk0, *p_Wpk1;
    cudaGetSymbolAddress((void**)&p_y0,  g_y0);
    cudaGetSymbolAddress((void**)&p_gx0, g_gx0);
    cudaGetSymbolAddress((void**)&p_gx1, g_gx1);
    cudaGetSymbolAddress((void**)&p_A2y0, g_A2y0);
    cudaGetSymbolAddress((void**)&p_A2out, g_A2out);
    cudaGetSymbolAddress((void**)&p_Wb2, g_Wb2);
    cudaGetSymbolAddress((void**)&p_Wih1b2, g_Wih1b2);
    cudaGetSymbolAddress((void**)&p_Wpk0, g_Wpk0);
    cudaGetSymbolAddress((void**)&p_Wpk1, g_Wpk1);

    cudaFuncSetAttribute(gemm_mma, cudaFuncAttributeMaxDynamicSharedMemorySize, GSM);
    cudaFuncSetAttribute(gru_scan_t, cudaFuncAttributeMaxDynamicSharedMemorySize, SCAN_SMEM);

    // index 3 = gru_scan_t layer 0 (profiled)
    k_wpack_scan<<<1536, 256>>>(W_hh0, p_Wpk0);                         // 0
    k_h0<<<B_*H_/256, 256>>>(z, W_init, b_init);                        // 1
    k_gx0<<<G3_/256, 256>>>(emb, W_ih0, b_ih0);                         // 2
    gru_scan_t<<<B_/16, 256, SCAN_SMEM>>>(p_Wpk0, b_hh0, p_gx0, 0, nullptr, 0);  // 3

    k_wpack_scan<<<1536, 256>>>(W_hh1, p_Wpk1);                         // 4
    k_wsplit<<<G3_, 256>>>(W_ih1, p_Wih1b2, G3_);                       // 5
    k_wsplit<<<PPAD, 256>>>(W_out, p_Wb2, P_);                          // 6

    // gx1 = y0 @ W_ih1^T + b_ih1
    gemm_mma<<<dim3(G3_/128, BT_/256), 256, GSM>>>(p_A2y0, p_Wih1b2, b_ih1, p_gx1, G3_, G3_);

    // layer 1 scan -> fp32 y
    gru_scan_t<<<B_/16, 256, SCAN_SMEM>>>(p_Wpk1, b_hh1, p_gx1, 1, p_y0, 1);

    // LayerNorm + ELU -> split bf16 A
    k_ln_elu<<<BT_/8, 256>>>(p_y0, ln_g, ln_b);

    // logits = yln @ W_out^T + b_out
    gemm_mma<<<dim3(PPAD/128, BT_/256), 256, GSM>>>(p_A2out, p_Wb2, b_out, (float*)d_out, P_, P_);
}

// round 8
// speedup vs baseline: 1.5743x; 1.5743x over previous
#include <cuda_runtime.h>
#include <cuda_fp16.h>
#include <cstdint>
#include <math.h>

#define B_  512
#define Z_  64
#define H_  256
#define T_  64
#define P_  10000
#define G3_ 768
#define BT_ (B_*T_)
#define PPAD 10112   // 79*128
#define KS_ 512      // fp16 2-term split: [Ah, Al] x [Wh, Wh]

// ---------------- scratch (no allocations allowed) ----------------
__device__ float g_h0[B_*H_];
__device__ float g_gx0[G3_];
__device__ float g_WT0[H_*G3_];
__device__ float g_WT1[H_*G3_];
__device__ float g_y0[BT_*H_];
__device__ float g_gx1[(size_t)BT_*G3_];
__device__ __align__(256) __half g_A2y0[(size_t)BT_*KS_];
__device__ __align__(256) __half g_A2out[(size_t)BT_*KS_];
__device__ __align__(256) __half g_Wb2[(size_t)PPAD*KS_];
__device__ __align__(256) __half g_Wih1b2[(size_t)G3_*KS_];

__device__ __forceinline__ float elu1(float x) {
    return x > 0.f ? x : (__expf(x) - 1.f);
}

__device__ __forceinline__ uint32_t smem_u32(const void* p) {
    uint32_t a;
    asm("{ .reg .u64 t; cvta.to.shared.u64 t, %1; cvt.u32.u64 %0, t; }" : "=r"(a) : "l"(p));
    return a;
}
__device__ __forceinline__ void cp16(uint32_t s, const void* g) {
    asm volatile("cp.async.cg.shared.global [%0], [%1], 16;" :: "r"(s), "l"(g));
}
__device__ __forceinline__ void ldsm4(uint32_t& a0, uint32_t& a1, uint32_t& a2, uint32_t& a3,
                                      uint32_t addr) {
    asm volatile("ldmatrix.sync.aligned.m8n8.x4.shared.b16 {%0,%1,%2,%3}, [%4];"
        : "=r"(a0), "=r"(a1), "=r"(a2), "=r"(a3) : "r"(addr));
}
__device__ __forceinline__ void mma16816(float* d, uint32_t a0, uint32_t a1, uint32_t a2,
                                         uint32_t a3, uint32_t b0, uint32_t b1) {
    asm volatile("mma.sync.aligned.m16n8k16.row.col.f32.f16.f16.f32 "
        "{%0,%1,%2,%3}, {%4,%5,%6,%7}, {%8,%9}, {%0,%1,%2,%3};"
        : "+f"(d[0]), "+f"(d[1]), "+f"(d[2]), "+f"(d[3])
        : "r"(a0), "r"(a1), "r"(a2), "r"(a3), "r"(b0), "r"(b1));
}

// ================= fp16 split-K tensor GEMM: C[M,ldc] = A2[M,512] @ B2[N,512]^T + bias
// 256x128 CTA tile, 8 warps (4 m x 2 n), warp tile 64x64, K chunks of 64.
// 3-stage cp.async pipeline, one __syncthreads per chunk. occ=1.
#define NCH (KS_/64)        // 8 K-chunks
#define ST_B 49152          // bytes per stage (A 32KB + B 16KB)
#define GSM  (3 * ST_B)     // 144 KB
__global__ __launch_bounds__(256, 1) void gemm_mma(
        const __half* __restrict__ A2, const __half* __restrict__ B2,
        const float* __restrict__ bias, float* __restrict__ C, int N, int ldc) {
    extern __shared__ char sm[];
    const uint32_t sbase = smem_u32(sm);
    const int tid = threadIdx.x, lane = tid & 31, wid = tid >> 5;
    const int m0t = blockIdx.y << 8, n0t = blockIdx.x << 7;

    uint32_t aSoff[8];
#pragma unroll
    for (int j = 0; j < 8; ++j)
        aSoff[j] = (uint32_t)(tid * 128 + ((j << 4) ^ ((tid & 7) << 4)));
    const char* gAr = (const char*)A2 + (size_t)(m0t + tid) * (KS_ * 2);
    const int brow = tid >> 1, bj0 = (tid & 1) * 4;
    uint32_t bSoff[4];
#pragma unroll
    for (int j = 0; j < 4; ++j)
        bSoff[j] = (uint32_t)(32768 + brow * 128 + (((bj0 + j) << 4) ^ ((brow & 7) << 4)));
    const char* gBr = (const char*)B2 + (size_t)(n0t + brow) * (KS_ * 2) + bj0 * 16;

    const int g = lane >> 3, r = lane & 7;
    const uint32_t rx = r << 4;
    const uint32_t aKbx = (g >> 1) << 4;
    const uint32_t bKbx = (g & 1) << 4;
    uint32_t aRowOff[4], bRowOff[4];
#pragma unroll
    for (int fm = 0; fm < 4; ++fm)
        aRowOff[fm] = (uint32_t)(((wid & 3) * 64 + ((g & 1) << 3) + r + fm * 16) * 128);
#pragma unroll
    for (int p = 0; p < 4; ++p)
        bRowOff[p] = (uint32_t)(32768 + ((wid >> 2) * 64 + ((g >> 1) << 3) + r + p * 16) * 128);

    float acc[4][8][4];
#pragma unroll
    for (int i = 0; i < 4; ++i)
#pragma unroll
        for (int j = 0; j < 8; ++j)
#pragma unroll
            for (int k = 0; k < 4; ++k) acc[i][j][k] = 0.f;

#pragma unroll
    for (int c = 0; c < 2; ++c) {
        const uint32_t sa = sbase + c * ST_B;
#pragma unroll
        for (int j = 0; j < 8; ++j) cp16(sa + aSoff[j], gAr + c * 128 + j * 16);
#pragma unroll
        for (int j = 0; j < 4; ++j) cp16(sa + bSoff[j], gBr + c * 128 + j * 16);
        asm volatile("cp.async.commit_group;");
    }

    int stage = 0, nstage = 2;
    for (int c = 0; c < NCH; ++c) {
        if (c < NCH - 1) asm volatile("cp.async.wait_group 1;");
        else             asm volatile("cp.async.wait_group 0;");
        __syncthreads();

        if (c + 2 < NCH) {
            const uint32_t sa = sbase + nstage * ST_B;
#pragma unroll
            for (int j = 0; j < 8; ++j) cp16(sa + aSoff[j], gAr + (c + 2) * 128 + j * 16);
#pragma unroll
            for (int j = 0; j < 4; ++j) cp16(sa + bSoff[j], gBr + (c + 2) * 128 + j * 16);
            asm volatile("cp.async.commit_group;");
        }

        const uint32_t sB = sbase + stage * ST_B;
#pragma unroll
        for (int kk = 0; kk < 4; ++kk) {
            const uint32_t akoff = ((uint32_t)(kk * 32) + aKbx) ^ rx;
            const uint32_t bkoff = ((uint32_t)(kk * 32) + bKbx) ^ rx;
            uint32_t a[4][4], bb[4][4];
#pragma unroll
            for (int fm = 0; fm < 4; ++fm)
                ldsm4(a[fm][0], a[fm][1], a[fm][2], a[fm][3], sB + aRowOff[fm] + akoff);
#pragma unroll
            for (int p = 0; p < 4; ++p)
                ldsm4(bb[p][0], bb[p][1], bb[p][2], bb[p][3], sB + bRowOff[p] + bkoff);
#pragma unroll
            for (int fm = 0; fm < 4; ++fm)
#pragma unroll
                for (int p = 0; p < 4; ++p) {
                    mma16816(acc[fm][2 * p],     a[fm][0], a[fm][1], a[fm][2], a[fm][3],
                             bb[p][0], bb[p][1]);
                    mma16816(acc[fm][2 * p + 1], a[fm][0], a[fm][1], a[fm][2], a[fm][3],
                             bb[p][2], bb[p][3]);
                }
        }
        stage  = (stage  == 2) ? 0 : stage  + 1;
        nstage = (nstage == 2) ? 0 : nstage + 1;
    }

#pragma unroll
    for (int fm = 0; fm < 4; ++fm) {
        const int mrow = m0t + (wid & 3) * 64 + fm * 16 + (lane >> 2);
        float* c0 = C + (size_t)mrow * ldc;
        float* c1 = C + (size_t)(mrow + 8) * ldc;
#pragma unroll
        for (int bn = 0; bn < 8; ++bn) {
            const int n = n0t + (wid >> 2) * 64 + bn * 8 + (lane & 3) * 2;
            if (n < N) {
                const float bv = bias[n];
                c0[n] = acc[fm][bn][0] + bv;
                c1[n] = acc[fm][bn][2] + bv;
            }
            if (n + 1 < N) {
                const float bv = bias[n + 1];
                c0[n + 1] = acc[fm][bn][1] + bv;
                c1[n + 1] = acc[fm][bn][3] + bv;
            }
        }
    }
}

// ---------------- prep kernels ----------------
__global__ void k_transpose(const float* __restrict__ W, float* __restrict__ WT) {
    int idx = blockIdx.x * 256 + threadIdx.x;
    int k = idx / G3_, g = idx - k * G3_;
    WT[idx] = W[g * H_ + k];
}

__global__ void k_h0(const float* __restrict__ z, const float* __restrict__ Wi,
                     const float* __restrict__ bi) {
    int idx = blockIdx.x * 256 + threadIdx.x;
    int b = idx >> 8, h = idx & 255;
    float s = bi[h];
    const float* zr = z + b * Z_;
    const float* wr = Wi + h * Z_;
#pragma unroll 16
    for (int i = 0; i < Z_; i++) s += zr[i] * wr[i];
    g_h0[idx] = elu1(s);
}

__global__ void k_gx0(const float* __restrict__ emb, const float* __restrict__ Wih,
                      const float* __restrict__ bih) {
    int gg = blockIdx.x * 256 + threadIdx.x;
    float s = bih[gg];
    const float* wr = Wih + gg * H_;
#pragma unroll 8
    for (int i = 0; i < H_; i++) s += emb[i] * wr[i];
    g_gx0[gg] = s;
}

// weights: [Wh, Wh]  (fp16)
__global__ void k_wsplit(const float* __restrict__ W, __half* __restrict__ O, int N) {
    int idx = blockIdx.x * 256 + threadIdx.x;
    int row = idx >> 8, col = idx & 255;
    float x = (row < N) ? W[row * 256 + col] : 0.f;
    __half h = __float2half(x);
    size_t base = (size_t)row * KS_;
    O[base + col]       = h;
    O[base + 256 + col] = h;
}

// activations: [Ah, Al]  (fp16 exact 2-term split)
__device__ __forceinline__ void store_act_split(__half* dst, size_t row, int col, float v) {
    __half hi = __float2half(v);
    float lo = v - __half2float(hi);
    size_t base = row * KS_;
    dst[base + col]       = hi;
    dst[base + 256 + col] = __float2half(lo);
}

// ---------------- GRU scan: 384 threads (scalar, reverted to R6 version) ----------------
#define BB 4
__global__ __launch_bounds__(384) void gru_scan(
        const float* __restrict__ WT, const float* __restrict__ bhh,
        const float* __restrict__ gx, int gx_per_bt,
        float* __restrict__ y, int out_mode) {   // 0: fp16 split -> g_A2y0 ; 1: fp32 -> y
    __shared__ __align__(16) float h_s [BB][H_];
    __shared__ __align__(16) float gh_s[BB][G3_];
    __shared__ __align__(16) float gx_s[BB][G3_];
    int tid = threadIdx.x;
    int b0 = blockIdx.x * BB;

    for (int i = tid; i < BB * H_; i += 384) h_s[i >> 8][i & 255] = g_h0[b0 * H_ + i];
    if (!gx_per_bt) {
        for (int i = tid; i < G3_; i += 384) gx_s[0][i] = gx[i];
    }
    float2 bias2 = *(const float2*)(bhh + tid * 2);
    __syncthreads();

    for (int step = 0; step < T_; step++) {
        if (gx_per_bt) {
#pragma unroll
            for (int i = 0; i < 2; ++i) {
                int idx = tid + i * 384;
                int rr = idx / 192;
                int c4 = (idx - rr * 192) * 4;
                *(float4*)&gx_s[rr][c4] =
                    *(const float4*)&gx[((size_t)(b0 + rr) * T_ + step) * G3_ + c4];
            }
        }
        float acc[BB][2];
#pragma unroll
        for (int rr = 0; rr < BB; rr++) { acc[rr][0] = 0.f; acc[rr][1] = 0.f; }
        {
            const float* wp = WT + tid * 2;
#pragma unroll 4
            for (int k = 0; k < H_; k += 4) {
                float2 w0 = *(const float2*)(wp + (size_t)(k+0) * G3_);
                float2 w1 = *(const float2*)(wp + (size_t)(k+1) * G3_);
                float2 w2 = *(const float2*)(wp + (size_t)(k+2) * G3_);
                float2 w3 = *(const float2*)(wp + (size_t)(k+3) * G3_);
#pragma unroll
                for (int rr = 0; rr < BB; rr++) {
                    float4 hv = *(const float4*)&h_s[rr][k];
                    acc[rr][0] += hv.x*w0.x + hv.y*w1.x + hv.z*w2.x + hv.w*w3.x;
                    acc[rr][1] += hv.x*w0.y + hv.y*w1.y + hv.z*w2.y + hv.w*w3.y;
                }
            }
#pragma unroll
            for (int rr = 0; rr < BB; rr++) {
                float2 gv = make_float2(acc[rr][0] + bias2.x, acc[rr][1] + bias2.y);
                *(float2*)&gh_s[rr][tid * 2] = gv;
            }
        }
        __syncthreads();
        if (tid < H_) {
#pragma unroll
            for (int rr = 0; rr < BB; rr++) {
                int gr = gx_per_bt ? rr : 0;
                float xr = gx_s[gr][tid], xz = gx_s[gr][H_+tid], xn = gx_s[gr][2*H_+tid];
                float hr = gh_s[rr][tid], hz = gh_s[rr][H_+tid], hn = gh_s[rr][2*H_+tid];
                float rg = 1.f / (1.f + __expf(-(xr + hr)));
                float ug = 1.f / (1.f + __expf(-(xz + hz)));
                float ng = tanhf(xn + rg * hn);
                float hold = h_s[rr][tid];
                float hnew = (1.f - ug) * ng + ug * hold;
                h_s[rr][tid] = hnew;
                size_t row = (size_t)(b0 + rr) * T_ + step;
                if (out_mode == 0) store_act_split(g_A2y0, row, tid, hnew);
                else               y[row * H_ + tid] = hnew;
            }
        }
        __syncthreads();
    }
}

// ---------------- LayerNorm + ELU -> fp16 split ----------------
__global__ void k_ln_elu(const float* __restrict__ y, const float* __restrict__ lng,
                         const float* __restrict__ lnb) {
    int warp = threadIdx.x >> 5, lane = threadIdx.x & 31;
    int row = blockIdx.x * 8 + warp;
    const float* p = y + (size_t)row * H_;
    float v[8], s = 0.f, sq = 0.f;
#pragma unroll
    for (int i = 0; i < 8; i++) { v[i] = p[lane + 32*i]; s += v[i]; sq += v[i]*v[i]; }
#pragma unroll
    for (int o = 16; o; o >>= 1) {
        s  += __shfl_xor_sync(0xffffffffu, s,  o);
        sq += __shfl_xor_sync(0xffffffffu, sq, o);
    }
    float mu  = s  * (1.f / H_);
    float var = sq * (1.f / H_) - mu * mu;
    float inv = rsqrtf(var + 1e-5f);
#pragma unroll
    for (int i = 0; i < 8; i++) {
        int c = lane + 32*i;
        float t = elu1((v[i] - mu) * inv * lng[c] + lnb[c]);
        store_act_split(g_A2out, (size_t)row, c, t);
    }
}

// ---------------- launch ----------------
extern "C" void kernel_launch(void* const* d_in, const int* in_sizes, int n_in,
                              void* d_out, int out_size) {
    const float* z      = (const float*)d_in[0];
    const float* W_init = (const float*)d_in[1];
    const float* b_init = (const float*)d_in[2];
    const float* emb    = (const float*)d_in[3];
    const float* W_ih0  = (const float*)d_in[4];
    const float* W_hh0  = (const float*)d_in[5];
    const float* b_ih0  = (const float*)d_in[6];
    const float* b_hh0  = (const float*)d_in[7];
    const float* W_ih1  = (const float*)d_in[8];
    const float* W_hh1  = (const float*)d_in[9];
    const float* b_ih1  = (const float*)d_in[10];
    const float* b_hh1  = (const float*)d_in[11];
    const float* ln_g   = (const float*)d_in[12];
    const float* ln_b   = (const float*)d_in[13];
    const float* W_out  = (const float*)d_in[14];
    const float* b_out  = (const float*)d_in[15];

    float *p_WT0, *p_WT1, *p_y0, *p_gx0, *p_gx1;
    __half *p_A2y0, *p_A2out, *p_Wb2, *p_Wih1b2;
    cudaGetSymbolAddress((void**)&p_WT0, g_WT0);
    cudaGetSymbolAddress((void**)&p_WT1, g_WT1);
    cudaGetSymbolAddress((void**)&p_y0,  g_y0);
    cudaGetSymbolAddress((void**)&p_gx0, g_gx0);
    cudaGetSymbolAddress((void**)&p_gx1, g_gx1);
    cudaGetSymbolAddress((void**)&p_A2y0, g_A2y0);
    cudaGetSymbolAddress((void**)&p_A2out, g_A2out);
    cudaGetSymbolAddress((void**)&p_Wb2, g_Wb2);
    cudaGetSymbolAddress((void**)&p_Wih1b2, g_Wih1b2);

    cudaFuncSetAttribute(gemm_mma, cudaFuncAttributeMaxDynamicSharedMemorySize, GSM);

    // index 3 = gru_scan layer 0 (profiled)
    k_transpose<<<H_*G3_/256, 256>>>(W_hh0, p_WT0);                    // 0
    k_h0<<<B_*H_/256, 256>>>(z, W_init, b_init);                       // 1
    k_gx0<<<G3_/256, 256>>>(emb, W_ih0, b_ih0);                        // 2
    gru_scan<<<B_/BB, 384>>>(p_WT0, b_hh0, p_gx0, 0, nullptr, 0);      // 3

    k_transpose<<<H_*G3_/256, 256>>>(W_hh1, p_WT1);                    // 4
    k_wsplit<<<G3_, 256>>>(W_ih1, p_Wih1b2, G3_);                      // 5
    k_wsplit<<<PPAD, 256>>>(W_out, p_Wb2, P_);                         // 6

    // gx1 = y0 @ W_ih1^T + b_ih1
    gemm_mma<<<dim3(G3_/128, BT_/256), 256, GSM>>>(p_A2y0, p_Wih1b2, b_ih1, p_gx1, G3_, G3_);

    // layer 1 scan -> fp32 y
    gru_scan<<<B_/BB, 384>>>(p_WT1, b_hh1, p_gx1, 1, p_y0, 1);

    // LayerNorm + ELU -> fp16 split A
    k_ln_elu<<<BT_/8, 256>>>(p_y0, ln_g, ln_b);

    // logits = yln @ W_out^T + b_out
    gemm_mma<<<dim3(PPAD/128, BT_/256), 256, GSM>>>(p_A2out, p_Wb2, b_out, (float*)d_out, P_, P_);
}